// round 7
// baseline (speedup 1.0000x reference)
#include <cuda_runtime.h>
#include <cuda_bf16.h>
#include <cstdint>

// Problem constants (from reference)
#define BATCH 16384
#define EMBED 1024
#define SEQ   7
#define E4    (EMBED / 4)       // 256 float4 lanes per full row
#define EQ4   64                // float4 lanes per quarter (256 channels)
#define NQ    4                 // number of channel quarters (launches)
#define ROWS_PER_CTA 8
#define THREADS 256

typedef unsigned long long u64;

// ---- f32x2 packed helpers (Blackwell) ----
__device__ __forceinline__ u64 pack2(float lo, float hi) {
    u64 r; asm("mov.b64 %0, {%1,%2};" : "=l"(r) : "f"(lo), "f"(hi)); return r;
}
__device__ __forceinline__ void unpack2(u64 v, float& lo, float& hi) {
    asm("mov.b64 {%0,%1}, %2;" : "=f"(lo), "=f"(hi) : "l"(v));
}
__device__ __forceinline__ u64 fma2(u64 a, u64 b, u64 c) {
    u64 d; asm("fma.rn.f32x2 %0, %1, %2, %3;" : "=l"(d) : "l"(a), "l"(b), "l"(c));
    return d;
}
__device__ __forceinline__ u64 mul2(u64 a, u64 b) {
    u64 d; asm("mul.rn.f32x2 %0, %1, %2;" : "=l"(d) : "l"(a), "l"(b));
    return d;
}
// packed tanh via two scalar MUFU ops
__device__ __forceinline__ u64 tanh2(u64 z) {
    float lo, hi;
    unpack2(z, lo, hi);
    asm("tanh.approx.f32 %0, %0;" : "+f"(lo));
    asm("tanh.approx.f32 %0, %0;" : "+f"(hi));
    return pack2(lo, hi);
}

// scaled float4 -> two packed f32x2
__device__ __forceinline__ ulonglong2 pack4s(float4 v, float s) {
    ulonglong2 r;
    r.x = pack2(v.x * s, v.y * s);
    r.y = pack2(v.z * s, v.w * s);
    return r;
}

// Tanh-domain cascade for one row (two packed channel-pair streams).
__device__ __forceinline__ void cascade_store(
    const ulonglong2 (*__restrict__ Wsm)[EQ4], int lane,
    const u64* __restrict__ ha, const u64* __restrict__ hb,
    float4* __restrict__ dst)
{
    const u64 HALF2 = pack2(0.5f, 0.5f);

    // Stage 1 (size-2, raw input, scale 1/2, no bias)
    ulonglong2 W0 = Wsm[0][lane], W1 = Wsm[1][lane];
    u64 pa[6], pb[6];
#pragma unroll
    for (int t = 0; t < 6; ++t) {
        pa[t] = tanh2(fma2(W0.x, ha[t], mul2(W1.x, ha[t + 1])));
        pb[t] = tanh2(fma2(W0.y, hb[t], mul2(W1.y, hb[t + 1])));
    }

    // Stage 2 (size-2, tanh-domain, scale 1/4 + bias)
    ulonglong2 V0 = Wsm[2][lane], V1 = Wsm[3][lane], B2 = Wsm[4][lane];
    u64 qa[5], qb[5];
#pragma unroll
    for (int t = 0; t < 5; ++t) {
        qa[t] = tanh2(fma2(V0.x, pa[t], fma2(V1.x, pa[t + 1], B2.x)));
        qb[t] = tanh2(fma2(V0.y, pb[t], fma2(V1.y, pb[t + 1], B2.y)));
    }

    // Stage 3 (size-3)
    ulonglong2 U0 = Wsm[5][lane], U1 = Wsm[6][lane], U2 = Wsm[7][lane],
               B3 = Wsm[8][lane];
    u64 sa[3], sb[3];
#pragma unroll
    for (int t = 0; t < 3; ++t) {
        sa[t] = tanh2(fma2(U0.x, qa[t],
                    fma2(U1.x, qa[t + 1], fma2(U2.x, qa[t + 2], B3.x))));
        sb[t] = tanh2(fma2(U0.y, qb[t],
                    fma2(U1.y, qb[t + 1], fma2(U2.y, qb[t + 2], B3.y))));
    }

    // Stage 4 (size-3) + final affine back to sigma
    ulonglong2 T0 = Wsm[9][lane], T1 = Wsm[10][lane], T2 = Wsm[11][lane],
               B4 = Wsm[12][lane];
    u64 ra = tanh2(fma2(T0.x, sa[0],
                   fma2(T1.x, sa[1], fma2(T2.x, sa[2], B4.x))));
    u64 rb = tanh2(fma2(T0.y, sb[0],
                   fma2(T1.y, sb[1], fma2(T2.y, sb[2], B4.y))));
    ra = fma2(ra, HALF2, HALF2);
    rb = fma2(rb, HALF2, HALF2);

    float4 res;
    unpack2(ra, res.x, res.y);
    unpack2(rb, res.z, res.w);
    __stcs(dst, res);
}

// One launch processes channel quarter [e4_base, e4_base+EQ4) float4-lanes
// for the whole batch (gather footprint 32.7MB -> L2-resident).
// Each thread handles TWO batch rows; all 14 gathers front-batched for MLP.
__global__ void __launch_bounds__(THREADS, 3)
conv_cascade_q_kernel(const int* __restrict__ X,
                      const ulonglong2* __restrict__ emb, // (VOCAB, E4) float4
                      const float4* __restrict__ c1,      // (2, E4)
                      const float4* __restrict__ c2,      // (2, E4)
                      const float4* __restrict__ c3,      // (3, E4)
                      const float4* __restrict__ c4,      // (3, E4)
                      float4* __restrict__ out,           // (BATCH, E4)
                      int e4_base)
{
    const int lane = threadIdx.x & (EQ4 - 1);           // 0..63
    const int rsub = threadIdx.x >> 6;                  // 0..3
    const int e4   = e4_base + lane;
    const int b0   = blockIdx.x * ROWS_PER_CTA;

    // Tanh-domain scaled weights, one set per lane, computed once.
    __shared__ ulonglong2 Wsm[13][EQ4];
    __shared__ int idx[ROWS_PER_CTA][SEQ];

    if (threadIdx.x < ROWS_PER_CTA * SEQ) {
        int r = threadIdx.x / SEQ;
        int t = threadIdx.x % SEQ;
        idx[r][t] = X[(b0 + r) * SEQ + t];
    }

    if (threadIdx.x < EQ4) {
        const int l = threadIdx.x;
        const int g = e4_base + l;
        float4 a0 = c1[0 * E4 + g], a1 = c1[1 * E4 + g];
        float4 d0 = c2[0 * E4 + g], d1 = c2[1 * E4 + g];
        float4 e0 = c3[0 * E4 + g], e1 = c3[1 * E4 + g], e2 = c3[2 * E4 + g];
        float4 f0 = c4[0 * E4 + g], f1 = c4[1 * E4 + g], f2 = c4[2 * E4 + g];

        Wsm[0][l] = pack4s(a0, 0.5f);
        Wsm[1][l] = pack4s(a1, 0.5f);
        Wsm[2][l] = pack4s(d0, 0.25f);
        Wsm[3][l] = pack4s(d1, 0.25f);
        float4 b2 = make_float4(d0.x + d1.x, d0.y + d1.y, d0.z + d1.z, d0.w + d1.w);
        Wsm[4][l] = pack4s(b2, 0.25f);
        Wsm[5][l] = pack4s(e0, 0.25f);
        Wsm[6][l] = pack4s(e1, 0.25f);
        Wsm[7][l] = pack4s(e2, 0.25f);
        float4 b3 = make_float4(e0.x + e1.x + e2.x, e0.y + e1.y + e2.y,
                                e0.z + e1.z + e2.z, e0.w + e1.w + e2.w);
        Wsm[8][l] = pack4s(b3, 0.25f);
        Wsm[9][l]  = pack4s(f0, 0.25f);
        Wsm[10][l] = pack4s(f1, 0.25f);
        Wsm[11][l] = pack4s(f2, 0.25f);
        float4 b4 = make_float4(f0.x + f1.x + f2.x, f0.y + f1.y + f2.y,
                                f0.z + f1.z + f2.z, f0.w + f1.w + f2.w);
        Wsm[12][l] = pack4s(b4, 0.25f);
    }

    __syncthreads();

    const int r0 = rsub;            // rows this thread owns
    const int r1 = rsub + 4;

    // Front-batched gathers for BOTH rows: 14 independent LDG.128 in flight.
    u64 ha0[SEQ], hb0[SEQ], ha1[SEQ], hb1[SEQ];
#pragma unroll
    for (int t = 0; t < SEQ; ++t) {
        long row = (long)idx[r0][t];
        ulonglong2 v = __ldg(&emb[row * E4 + e4]);
        ha0[t] = v.x; hb0[t] = v.y;
    }
#pragma unroll
    for (int t = 0; t < SEQ; ++t) {
        long row = (long)idx[r1][t];
        ulonglong2 v = __ldg(&emb[row * E4 + e4]);
        ha1[t] = v.x; hb1[t] = v.y;
    }

    cascade_store(Wsm, lane, ha0, hb0, &out[(long)(b0 + r0) * E4 + e4]);
    cascade_store(Wsm, lane, ha1, hb1, &out[(long)(b0 + r1) * E4 + e4]);
}

extern "C" void kernel_launch(void* const* d_in, const int* in_sizes, int n_in,
                              void* d_out, int out_size)
{
    const int*        X    = (const int*)d_in[0];
    const ulonglong2* emb  = (const ulonglong2*)d_in[1];
    const float4*     c1   = (const float4*)d_in[2];
    const float4*     c2   = (const float4*)d_in[3];
    const float4*     c3   = (const float4*)d_in[4];
    const float4*     c4   = (const float4*)d_in[5];
    float4*           out  = (float4*)d_out;

    dim3 grid(BATCH / ROWS_PER_CTA);   // 2048 CTAs per launch
    dim3 block(THREADS);
    for (int q = 0; q < NQ; ++q) {
        conv_cascade_q_kernel<<<grid, block>>>(X, emb, c1, c2, c3, c4, out,
                                               q * EQ4);
    }
}